// round 8
// baseline (speedup 1.0000x reference)
#include <cuda_runtime.h>
#include <cstddef>

// Fixed problem shape: K=64, N=1048576, NS=1024, B=1024
constexpr int   Kdim   = 64;
constexpr long  Nn     = 1048576;
constexpr int   NSs    = 1024;
constexpr int   Bseq   = 1024;
constexpr int   TBLK   = 32;          // staging block (time steps) == renorm period
constexpr int   STRIDE = 36;          // staged row stride (floats), 16B-aligned rows
constexpr float L2E    = 1.4426950408889634f;
constexpr float LN2    = 0.6931471805599453f;

__device__ unsigned gT2[Kdim * 32];    // gT2[k*32+j] = bf16x2(Tp[2j][k], Tp[2j+1][k])
__device__ float    gTpF[Kdim * Kdim]; // fp32 row-softmax of T (for bias kernel)
__device__ float    gLpi2[Kdim];       // log_softmax(pi) * log2(e)
__device__ float    gLs[Kdim];         // per-state log2 correction for bf16(T) bias
__device__ float    gPart[Bseq];

// ---------------------------------------------------------------------------
// helpers
// ---------------------------------------------------------------------------
__device__ __forceinline__ float ex2f(float x) {
    float r; asm("ex2.approx.ftz.f32 %0, %1;" : "=f"(r) : "f"(x)); return r;
}
__device__ __forceinline__ float lg2f(float x) {
    float r; asm("lg2.approx.ftz.f32 %0, %1;" : "=f"(r) : "f"(x)); return r;
}
__device__ __forceinline__ float warp_sum(float v) {
#pragma unroll
    for (int o = 16; o > 0; o >>= 1) v += __shfl_xor_sync(0xffffffffu, v, o);
    return v;
}
__device__ __forceinline__ void hfma2(unsigned& acc, unsigned a, unsigned b) {
    asm("fma.rn.bf16x2 %0, %1, %2, %0;" : "+r"(acc) : "r"(a), "r"(b));
}
__device__ __forceinline__ unsigned hadd2(unsigned a, unsigned b) {
    unsigned r; asm("add.rn.bf16x2 %0, %1, %2;" : "=r"(r) : "r"(a), "r"(b)); return r;
}
__device__ __forceinline__ float blo(unsigned u) { return __uint_as_float(u << 16); }
__device__ __forceinline__ float bhi(unsigned u) { return __uint_as_float(u & 0xffff0000u); }
__device__ __forceinline__ unsigned pack_bf16x2(float lo, float hi) {
    unsigned r; asm("cvt.rn.bf16x2.f32 %0, %1, %2;" : "=r"(r) : "f"(hi), "f"(lo)); return r;
}
__device__ __forceinline__ float bf16r(float x) { return blo(pack_bf16x2(x, 0.f)); }
__device__ __forceinline__ void cpasync16(void* dst, const void* src) {
    unsigned d = (unsigned)__cvta_generic_to_shared(dst);
    asm volatile("cp.async.ca.shared.global [%0], [%1], 16;" :: "r"(d), "l"(src));
}
template <int N> __device__ __forceinline__ void wait_group() {
    asm volatile("cp.async.wait_group %0;" :: "n"(N));
}
__device__ __forceinline__ void commit_group() {
    asm volatile("cp.async.commit_group;");
}

// stage one 32-step emission block (64 rows x 32 floats) + commit
__device__ __forceinline__ void issue_stage(float* sbuf, const float* gbase, int l) {
#pragma unroll
    for (int i = 0; i < 16; i++) {
        int m   = (i << 5) + l;
        int row = m >> 3;
        int c4  = (m & 7) << 2;
        cpasync16(sbuf + row * STRIDE + c4, gbase + (size_t)row * Nn + c4);
    }
    commit_group();
}

// ---------------------------------------------------------------------------
// prep: softmax rows of T -> fp32 copy + bf16x2 pack; log_softmax(pi)
// ---------------------------------------------------------------------------
__global__ void __launch_bounds__(1024) prep_kernel(const float* __restrict__ pi,
                                                    const float* __restrict__ T) {
    __shared__ float sTp[Kdim * Kdim];
    int tid = threadIdx.x, w = tid >> 5, l = tid & 31;
#pragma unroll
    for (int r = w; r < Kdim; r += 32) {
        float a = T[r * Kdim + l], c = T[r * Kdim + l + 32];
        float m = fmaxf(a, c);
#pragma unroll
        for (int o = 16; o > 0; o >>= 1) m = fmaxf(m, __shfl_xor_sync(0xffffffffu, m, o));
        float ea = expf(a - m), ec = expf(c - m);
        float s = warp_sum(ea + ec);
        float inv = 1.0f / s;
        sTp[r * Kdim + l]      = ea * inv;
        sTp[r * Kdim + l + 32] = ec * inv;
    }
    __syncthreads();
    for (int idx = tid; idx < Kdim * Kdim; idx += 1024) gTpF[idx] = sTp[idx];
    for (int idx = tid; idx < Kdim * 32; idx += 1024) {
        int k = idx >> 5, j = idx & 31;
        gT2[idx] = pack_bf16x2(sTp[(2 * j) * Kdim + k], sTp[(2 * j + 1) * Kdim + k]);
    }
    if (w == 0) {  // log_softmax(pi)
        float pa = pi[l], pb = pi[l + 32];
        float m2 = fmaxf(pa, pb);
#pragma unroll
        for (int o = 16; o > 0; o >>= 1) m2 = fmaxf(m2, __shfl_xor_sync(0xffffffffu, m2, o));
        float sp = warp_sum(expf(pa - m2) + expf(pb - m2));
        float ls = logf(sp);
        gLpi2[l]      = (pa - m2 - ls) * L2E;
        gLpi2[l + 32] = (pb - m2 - ls) * L2E;
    }
}

// ---------------------------------------------------------------------------
// bias kernel (single warp): stationary distribution of Tp + per-column
// log2 correction for the coherent bf16(T) quantization bias
// ---------------------------------------------------------------------------
__global__ void bias_kernel() {
    int l = threadIdx.x;
    float wA = 1.0f / 64.0f, wB = 1.0f / 64.0f;
    for (int it = 0; it < 24; it++) {
        float nA = 0.f, nB = 0.f;
#pragma unroll
        for (int j = 0; j < 32; j++) {
            float wj0 = __shfl_sync(0xffffffffu, wA, j);
            float wj1 = __shfl_sync(0xffffffffu, wB, j);
            nA = fmaf(wj0, gTpF[(2 * j) * Kdim + 2 * l],     nA);
            nA = fmaf(wj1, gTpF[(2 * j + 1) * Kdim + 2 * l], nA);
            nB = fmaf(wj0, gTpF[(2 * j) * Kdim + 2 * l + 1],     nB);
            nB = fmaf(wj1, gTpF[(2 * j + 1) * Kdim + 2 * l + 1], nB);
        }
        float S = warp_sum(nA + nB);
        wA = nA / S; wB = nB / S;
    }
    float nA = 0.f, nB = 0.f, dA = 0.f, dB = 0.f;
#pragma unroll
    for (int j = 0; j < 32; j++) {
        float wj0 = __shfl_sync(0xffffffffu, wA, j);
        float wj1 = __shfl_sync(0xffffffffu, wB, j);
        float t00 = gTpF[(2 * j) * Kdim + 2 * l];
        float t10 = gTpF[(2 * j + 1) * Kdim + 2 * l];
        float t01 = gTpF[(2 * j) * Kdim + 2 * l + 1];
        float t11 = gTpF[(2 * j + 1) * Kdim + 2 * l + 1];
        nA += wj0 * t00 + wj1 * t10;
        nB += wj0 * t01 + wj1 * t11;
        dA += wj0 * bf16r(t00) + wj1 * bf16r(t10);
        dB += wj0 * bf16r(t01) + wj1 * bf16r(t11);
    }
    gLs[2 * l]     = log2f(nA / dA);
    gLs[2 * l + 1] = log2f(nB / dB);
}

// ---------------------------------------------------------------------------
// one forward step: q exchanged via smem ping-pong (1 STS.32 + 8 LDS.128 + 1 sync)
// lane l owns states (2l, 2l+1); q buffers hold 32 bf16x2 words
// ---------------------------------------------------------------------------
__device__ __forceinline__ void stepM(const unsigned* __restrict__ qR,
                                      unsigned* __restrict__ qW, int l,
                                      const unsigned* __restrict__ Ta,
                                      const unsigned* __restrict__ Tb,
                                      float fA, float fB,
                                      float& qA, float& qB) {
    __syncwarp();
    uint4 w[8];
    const uint4* qp = (const uint4*)qR;
#pragma unroll
    for (int i = 0; i < 8; i++) w[i] = qp[i];   // hoist all q loads (MLP)

    unsigned A0 = 0, A1 = 0, B0 = 0, B1 = 0;
#pragma unroll
    for (int i = 0; i < 8; i++) {
        hfma2(A0, w[i].x, Ta[4 * i + 0]); hfma2(B0, w[i].x, Tb[4 * i + 0]);
        hfma2(A1, w[i].y, Ta[4 * i + 1]); hfma2(B1, w[i].y, Tb[4 * i + 1]);
        hfma2(A0, w[i].z, Ta[4 * i + 2]); hfma2(B0, w[i].z, Tb[4 * i + 2]);
        hfma2(A1, w[i].w, Ta[4 * i + 3]); hfma2(B1, w[i].w, Tb[4 * i + 3]);
    }
    unsigned a = hadd2(A0, A1);
    unsigned b = hadd2(B0, B1);
    qA = fA * (blo(a) + bhi(a));     // fp32 final combine (unbiased)
    qB = fB * (blo(b) + bhi(b));
    qW[l] = pack_bf16x2(qA, qB);
}

// ---------------------------------------------------------------------------
// forward scan: one single-warp CTA per sequence (1024 CTAs)
// ---------------------------------------------------------------------------
__global__ void __launch_bounds__(32) fwd_kernel(const float* __restrict__ lp) {
    __shared__ float st[2][Kdim * STRIDE];                  // 18432 B
    __shared__ __align__(16) unsigned q0[32], q1[32];
    const int l = threadIdx.x;
    const float* base = lp + (size_t)blockIdx.x * NSs;

    issue_stage(st[0], base, l);
    issue_stage(st[1], base + TBLK, l);

    unsigned Ta[32], Tb[32];
    {
        const uint4* pa = (const uint4*)(gT2 + (2 * l) * 32);
        const uint4* pb = (const uint4*)(gT2 + (2 * l + 1) * 32);
#pragma unroll
        for (int i = 0; i < 8; i++) { ((uint4*)Ta)[i] = pa[i]; ((uint4*)Tb)[i] = pb[i]; }
    }
    const float lpiA = gLpi2[2 * l], lpiB = gLpi2[2 * l + 1];
    const float lsA  = gLs[2 * l],   lsB  = gLs[2 * l + 1];

    wait_group<1>();
    __syncwarp();

    // t = 0..3 (init + 3 steps), block 0. After these, live q is in q1,
    // and every subsequent group of 4 reads q1 first and ends in q1.
    float4 e4A = *(const float4*)(st[0] + (2 * l) * STRIDE);
    float4 e4B = *(const float4*)(st[0] + (2 * l + 1) * STRIDE);
    float qA = ex2f(fmaf(e4A.x, L2E, lpiA));
    float qB = ex2f(fmaf(e4B.x, L2E, lpiB));
    q0[l] = pack_bf16x2(qA, qB);
    {
        float fA1 = ex2f(fmaf(e4A.y, L2E, lsA)), fB1 = ex2f(fmaf(e4B.y, L2E, lsB));
        float fA2 = ex2f(fmaf(e4A.z, L2E, lsA)), fB2 = ex2f(fmaf(e4B.z, L2E, lsB));
        float fA3 = ex2f(fmaf(e4A.w, L2E, lsA)), fB3 = ex2f(fmaf(e4B.w, L2E, lsB));
        stepM(q0, q1, l, Ta, Tb, fA1, fB1, qA, qB);
        stepM(q1, q0, l, Ta, Tb, fA2, fB2, qA, qB);
        stepM(q0, q1, l, Ta, Tb, fA3, fB3, qA, qB);
    }

    double cacc = 0.0;
    float  gp   = 0.0f;

#pragma unroll 1
    for (int t0 = 4; t0 < NSs; t0 += 4) {
        if ((t0 & (TBLK - 1)) == 0) {
            // block boundary: renorm (every 32 steps) + staging swap
            float S = warp_sum(qA + qB);
            float g = lg2f(S);
            cacc += (double)g;
            gp = -g;
            wait_group<0>();
            __syncwarp();
            int k = t0 >> 5;
            if (t0 + TBLK < NSs)
                issue_stage(st[(k + 1) & 1], base + t0 + TBLK, l);
        }
        const float* sb = st[(t0 >> 5) & 1];
        const int tt = t0 & (TBLK - 1);
        float4 eA = *(const float4*)(sb + (2 * l) * STRIDE + tt);
        float4 eB = *(const float4*)(sb + (2 * l + 1) * STRIDE + tt);

        // off-chain f-factor precompute (bias correction + pending renorm)
        float aA = lsA + gp, aB = lsB + gp;
        float fA0 = ex2f(fmaf(eA.x, L2E, aA)),  fB0 = ex2f(fmaf(eB.x, L2E, aB));
        float fA1 = ex2f(fmaf(eA.y, L2E, lsA)), fB1 = ex2f(fmaf(eB.y, L2E, lsB));
        float fA2 = ex2f(fmaf(eA.z, L2E, lsA)), fB2 = ex2f(fmaf(eB.z, L2E, lsB));
        float fA3 = ex2f(fmaf(eA.w, L2E, lsA)), fB3 = ex2f(fmaf(eB.w, L2E, lsB));
        gp = 0.0f;

        // groups always start with live q in q1 (4 swaps return it to q1)
        stepM(q1, q0, l, Ta, Tb, fA0, fB0, qA, qB);
        stepM(q0, q1, l, Ta, Tb, fA1, fB1, qA, qB);
        stepM(q1, q0, l, Ta, Tb, fA2, fB2, qA, qB);
        stepM(q0, q1, l, Ta, Tb, fA3, fB3, qA, qB);
    }

    float S = warp_sum(qA + qB);
    if (l == 0) gPart[blockIdx.x] = LN2 * (float)(cacc + (double)lg2f(S));
}

// ---------------------------------------------------------------------------
// deterministic final reduction
// ---------------------------------------------------------------------------
__global__ void reduce_kernel(float* __restrict__ out) {
    __shared__ double s[256];
    int t = threadIdx.x;
    double v = 0.0;
    for (int i = t; i < Bseq; i += 256) v += (double)gPart[i];
    s[t] = v;
    __syncthreads();
    for (int o = 128; o > 0; o >>= 1) {
        if (t < o) s[t] += s[t + o];
        __syncthreads();
    }
    if (t == 0) out[0] = (float)s[0];
}

// ---------------------------------------------------------------------------
extern "C" void kernel_launch(void* const* d_in, const int* in_sizes, int n_in,
                              void* d_out, int out_size) {
    const float* lp = (const float*)d_in[0];  // log_pdf (K, N)
    const float* pi = (const float*)d_in[1];  // pi (K,)
    const float* T  = (const float*)d_in[2];  // T (K, K)
    (void)in_sizes; (void)n_in; (void)out_size;

    prep_kernel<<<1, 1024>>>(pi, T);
    bias_kernel<<<1, 32>>>();
    fwd_kernel<<<Bseq, 32>>>(lp);
    reduce_kernel<<<1, 256>>>((float*)d_out);
}

// round 9
// speedup vs baseline: 1.5470x; 1.5470x over previous
#include <cuda_runtime.h>
#include <cstddef>

// Fixed problem shape: K=64, N=1048576, NS=1024, B=1024
constexpr int   Kdim   = 64;
constexpr long  Nn     = 1048576;
constexpr int   NSs    = 1024;
constexpr int   Bseq   = 1024;
constexpr int   TBLK   = 32;          // staging block (time steps)
constexpr int   STRIDE = 36;          // staged row stride (floats), 16B-aligned rows
constexpr float L2E    = 1.4426950408889634f;
constexpr float LN2    = 0.6931471805599453f;

__device__ unsigned gT2[Kdim * 32];    // gT2[k*32+j] = bf16x2(Tp[2j][k], Tp[2j+1][k])
__device__ float    gTpF[Kdim * Kdim]; // fp32 row-softmax of T (for bias kernel)
__device__ float    gLpi2[Kdim];       // log_softmax(pi) * log2(e)
__device__ float    gLs[Kdim];         // per-state log2 correction for bf16(T) bias
__device__ float    gPart[Bseq];

// ---------------------------------------------------------------------------
// helpers
// ---------------------------------------------------------------------------
__device__ __forceinline__ float ex2f(float x) {
    float r; asm("ex2.approx.ftz.f32 %0, %1;" : "=f"(r) : "f"(x)); return r;
}
__device__ __forceinline__ float lg2f(float x) {
    float r; asm("lg2.approx.ftz.f32 %0, %1;" : "=f"(r) : "f"(x)); return r;
}
__device__ __forceinline__ float warp_sum(float v) {
#pragma unroll
    for (int o = 16; o > 0; o >>= 1) v += __shfl_xor_sync(0xffffffffu, v, o);
    return v;
}
__device__ __forceinline__ void hfma2(unsigned& acc, unsigned a, unsigned b) {
    asm("fma.rn.bf16x2 %0, %1, %2, %0;" : "+r"(acc) : "r"(a), "r"(b));
}
__device__ __forceinline__ unsigned hadd2(unsigned a, unsigned b) {
    unsigned r; asm("add.rn.bf16x2 %0, %1, %2;" : "=r"(r) : "r"(a), "r"(b)); return r;
}
__device__ __forceinline__ float blo(unsigned u) { return __uint_as_float(u << 16); }
__device__ __forceinline__ float bhi(unsigned u) { return __uint_as_float(u & 0xffff0000u); }
__device__ __forceinline__ unsigned pack_bf16x2(float lo, float hi) {
    unsigned r; asm("cvt.rn.bf16x2.f32 %0, %1, %2;" : "=r"(r) : "f"(hi), "f"(lo)); return r;
}
__device__ __forceinline__ float bf16r(float x) { return blo(pack_bf16x2(x, 0.f)); }
__device__ __forceinline__ void cpasync16(void* dst, const void* src) {
    unsigned d = (unsigned)__cvta_generic_to_shared(dst);
    asm volatile("cp.async.ca.shared.global [%0], [%1], 16;" :: "r"(d), "l"(src));
}
template <int N> __device__ __forceinline__ void wait_group() {
    asm volatile("cp.async.wait_group %0;" :: "n"(N));
}
__device__ __forceinline__ void commit_group() {
    asm volatile("cp.async.commit_group;");
}

// issue one 32-step emission block (64 rows x 32 floats) into staging buffer
__device__ __forceinline__ void issue_stage(float* sbuf, const float* gbase, int l) {
#pragma unroll
    for (int i = 0; i < 16; i++) {
        int m   = (i << 5) + l;
        int row = m >> 3;
        int c4  = (m & 7) << 2;
        cpasync16(sbuf + row * STRIDE + c4, gbase + (size_t)row * Nn + c4);
    }
    commit_group();
}

// ---------------------------------------------------------------------------
// prep: softmax rows of T -> fp32 copy + bf16x2 pack; log_softmax(pi)
// ---------------------------------------------------------------------------
__global__ void __launch_bounds__(1024) prep_kernel(const float* __restrict__ pi,
                                                    const float* __restrict__ T) {
    __shared__ float sTp[Kdim * Kdim];
    int tid = threadIdx.x, w = tid >> 5, l = tid & 31;
#pragma unroll
    for (int r = w; r < Kdim; r += 32) {
        float a = T[r * Kdim + l], c = T[r * Kdim + l + 32];
        float m = fmaxf(a, c);
#pragma unroll
        for (int o = 16; o > 0; o >>= 1) m = fmaxf(m, __shfl_xor_sync(0xffffffffu, m, o));
        float ea = expf(a - m), ec = expf(c - m);
        float s = warp_sum(ea + ec);
        float inv = 1.0f / s;
        sTp[r * Kdim + l]      = ea * inv;
        sTp[r * Kdim + l + 32] = ec * inv;
    }
    __syncthreads();
    for (int idx = tid; idx < Kdim * Kdim; idx += 1024) gTpF[idx] = sTp[idx];
    for (int idx = tid; idx < Kdim * 32; idx += 1024) {
        int k = idx >> 5, j = idx & 31;
        gT2[idx] = pack_bf16x2(sTp[(2 * j) * Kdim + k], sTp[(2 * j + 1) * Kdim + k]);
    }
    if (w == 0) {  // log_softmax(pi)
        float pa = pi[l], pb = pi[l + 32];
        float m2 = fmaxf(pa, pb);
#pragma unroll
        for (int o = 16; o > 0; o >>= 1) m2 = fmaxf(m2, __shfl_xor_sync(0xffffffffu, m2, o));
        float sp = warp_sum(expf(pa - m2) + expf(pb - m2));
        float ls = logf(sp);
        gLpi2[l]      = (pa - m2 - ls) * L2E;
        gLpi2[l + 32] = (pb - m2 - ls) * L2E;
    }
}

// ---------------------------------------------------------------------------
// bias kernel (single warp): stationary distribution of Tp + per-column
// log2 correction for the coherent bf16(T) quantization bias
// ---------------------------------------------------------------------------
__global__ void bias_kernel() {
    int l = threadIdx.x;
    float wA = 1.0f / 64.0f, wB = 1.0f / 64.0f;
    for (int it = 0; it < 24; it++) {
        float nA = 0.f, nB = 0.f;
#pragma unroll
        for (int j = 0; j < 32; j++) {
            float wj0 = __shfl_sync(0xffffffffu, wA, j);
            float wj1 = __shfl_sync(0xffffffffu, wB, j);
            nA = fmaf(wj0, gTpF[(2 * j) * Kdim + 2 * l],     nA);
            nA = fmaf(wj1, gTpF[(2 * j + 1) * Kdim + 2 * l], nA);
            nB = fmaf(wj0, gTpF[(2 * j) * Kdim + 2 * l + 1],     nB);
            nB = fmaf(wj1, gTpF[(2 * j + 1) * Kdim + 2 * l + 1], nB);
        }
        float S = warp_sum(nA + nB);
        wA = nA / S; wB = nB / S;
    }
    float nA = 0.f, nB = 0.f, dA = 0.f, dB = 0.f;
#pragma unroll
    for (int j = 0; j < 32; j++) {
        float wj0 = __shfl_sync(0xffffffffu, wA, j);
        float wj1 = __shfl_sync(0xffffffffu, wB, j);
        float t00 = gTpF[(2 * j) * Kdim + 2 * l];
        float t10 = gTpF[(2 * j + 1) * Kdim + 2 * l];
        float t01 = gTpF[(2 * j) * Kdim + 2 * l + 1];
        float t11 = gTpF[(2 * j + 1) * Kdim + 2 * l + 1];
        nA += wj0 * t00 + wj1 * t10;
        nB += wj0 * t01 + wj1 * t11;
        dA += wj0 * bf16r(t00) + wj1 * bf16r(t10);
        dB += wj0 * bf16r(t01) + wj1 * bf16r(t11);
    }
    gLs[2 * l]     = log2f(nA / dA);
    gLs[2 * l + 1] = log2f(nB / dB);
}

// ---------------------------------------------------------------------------
// one forward step (R3 structure): smem ping-pong, per-iteration q loads.
// lane l owns states (2l, 2l+1); gpA/gpB = ls correction (+ pending renorm)
// ---------------------------------------------------------------------------
__device__ __forceinline__ void step(const unsigned* qR, unsigned* qW, int l,
                                     const unsigned* Ta, const unsigned* Tb,
                                     float eA, float eB, float gpA, float gpB,
                                     float& qA, float& qB) {
    __syncwarp();
    const uint4* qp = (const uint4*)qR;
    unsigned a0 = 0u, a1 = 0u, b0 = 0u, b1 = 0u;
#pragma unroll
    for (int i = 0; i < 8; i++) {
        uint4 w = qp[i];
        hfma2(a0, w.x, Ta[4 * i + 0]);  hfma2(b0, w.x, Tb[4 * i + 0]);
        hfma2(a1, w.y, Ta[4 * i + 1]);  hfma2(b1, w.y, Tb[4 * i + 1]);
        hfma2(a0, w.z, Ta[4 * i + 2]);  hfma2(b0, w.z, Tb[4 * i + 2]);
        hfma2(a1, w.w, Ta[4 * i + 3]);  hfma2(b1, w.w, Tb[4 * i + 3]);
    }
    unsigned a = hadd2(a0, a1), b = hadd2(b0, b1);
    float dA = blo(a) + bhi(a);          // fp32 final combine
    float dB = blo(b) + bhi(b);
    float fA = ex2f(fmaf(eA, L2E, gpA));
    float fB = ex2f(fmaf(eB, L2E, gpB));
    qA = fA * dA;
    qB = fB * dB;
    qW[l] = pack_bf16x2(qA, qB);
}

// ---------------------------------------------------------------------------
// forward scan: one single-warp CTA per sequence (1024 CTAs)
// ---------------------------------------------------------------------------
__global__ void __launch_bounds__(32) fwd_kernel(const float* __restrict__ lp) {
    __shared__ float st[2][Kdim * STRIDE];
    __shared__ __align__(16) unsigned q0[32], q1[32];
    const int l = threadIdx.x;
    const int b = blockIdx.x;
    const float* base = lp + (size_t)b * NSs;

    issue_stage(st[0], base, l);
    issue_stage(st[1], base + TBLK, l);

    unsigned Ta[32], Tb[32];
    {
        const uint4* pa = (const uint4*)(gT2 + (2 * l) * 32);
        const uint4* pb = (const uint4*)(gT2 + (2 * l + 1) * 32);
#pragma unroll
        for (int i = 0; i < 8; i++) { ((uint4*)Ta)[i] = pa[i]; ((uint4*)Tb)[i] = pb[i]; }
    }
    const float lpiA = gLpi2[2 * l], lpiB = gLpi2[2 * l + 1];
    const float lsA  = gLs[2 * l],   lsB  = gLs[2 * l + 1];

    wait_group<1>();
    __syncwarp();

    // t = 0: q = exp2(lp0*log2e + log2_pi); then t = 1..3 (live q ends in q1)
    float4 e4A = *(const float4*)(st[0] + (2 * l) * STRIDE);
    float4 e4B = *(const float4*)(st[0] + (2 * l + 1) * STRIDE);
    float qA = ex2f(fmaf(e4A.x, L2E, lpiA));
    float qB = ex2f(fmaf(e4B.x, L2E, lpiB));
    q0[l] = pack_bf16x2(qA, qB);
    step(q0, q1, l, Ta, Tb, e4A.y, e4B.y, lsA, lsB, qA, qB);
    step(q1, q0, l, Ta, Tb, e4A.z, e4B.z, lsA, lsB, qA, qB);
    step(q0, q1, l, Ta, Tb, e4A.w, e4B.w, lsA, lsB, qA, qB);

    double cacc = 0.0;
    float  gp   = 0.0f;   // pending -log2(scale), folded into next group's first exp

#pragma unroll 1
    for (int t0 = 4; t0 < NSs; t0 += 4) {
        if ((t0 & (TBLK - 1)) == 0) {
            wait_group<0>();
            __syncwarp();
            int k = t0 >> 5;
            if (t0 + TBLK < NSs)
                issue_stage(st[(k + 1) & 1], base + t0 + TBLK, l);
        }
        const float* sb = st[(t0 >> 5) & 1];
        const int tt = t0 & (TBLK - 1);
        float4 eA = *(const float4*)(sb + (2 * l) * STRIDE + tt);
        float4 eB = *(const float4*)(sb + (2 * l + 1) * STRIDE + tt);

        // groups always start with live q in q1 (4 swaps return it to q1)
        step(q1, q0, l, Ta, Tb, eA.x, eB.x, lsA + gp, lsB + gp, qA, qB);
        step(q0, q1, l, Ta, Tb, eA.y, eB.y, lsA, lsB, qA, qB);
        step(q1, q0, l, Ta, Tb, eA.z, eB.z, lsA, lsB, qA, qB);
        step(q0, q1, l, Ta, Tb, eA.w, eB.w, lsA, lsB, qA, qB);
        gp = 0.0f;

        if ((t0 & 15) == 4) {                  // renorm every 16 steps (off-chain)
            float S = warp_sum(qA + qB);
            float g = lg2f(S);
            cacc += (double)g;
            gp = -g;                           // applied via next group's first exp
        }
    }

    float S = warp_sum(qA + qB);
    if (l == 0) gPart[b] = LN2 * (float)(cacc + (double)lg2f(S));
}

// ---------------------------------------------------------------------------
// deterministic final reduction
// ---------------------------------------------------------------------------
__global__ void reduce_kernel(float* __restrict__ out) {
    __shared__ double s[256];
    int t = threadIdx.x;
    double v = 0.0;
    for (int i = t; i < Bseq; i += 256) v += (double)gPart[i];
    s[t] = v;
    __syncthreads();
    for (int o = 128; o > 0; o >>= 1) {
        if (t < o) s[t] += s[t + o];
        __syncthreads();
    }
    if (t == 0) out[0] = (float)s[0];
}

// ---------------------------------------------------------------------------
extern "C" void kernel_launch(void* const* d_in, const int* in_sizes, int n_in,
                              void* d_out, int out_size) {
    const float* lp = (const float*)d_in[0];  // log_pdf (K, N)
    const float* pi = (const float*)d_in[1];  // pi (K,)
    const float* T  = (const float*)d_in[2];  // T (K, K)
    (void)in_sizes; (void)n_in; (void)out_size;

    prep_kernel<<<1, 1024>>>(pi, T);
    bias_kernel<<<1, 32>>>();
    fwd_kernel<<<Bseq, 32>>>(lp);
    reduce_kernel<<<1, 256>>>((float*)d_out);
}

// round 10
// speedup vs baseline: 1.5605x; 1.0088x over previous
#include <cuda_runtime.h>
#include <cstddef>

// Fixed problem shape: K=64, N=1048576, NS=1024, B=1024
constexpr int   Kdim   = 64;
constexpr long  Nn     = 1048576;
constexpr int   NSs    = 1024;
constexpr int   Bseq   = 1024;
constexpr int   TBLK   = 32;          // staging block (time steps) == renorm period
constexpr int   STRIDE = 36;          // staged row stride (floats), 16B-aligned rows
constexpr float L2E    = 1.4426950408889634f;
constexpr float LN2    = 0.6931471805599453f;

__device__ unsigned gT2[Kdim * 32];    // gT2[k*32+j] = bf16x2(Tp[2j][k], Tp[2j+1][k])
__device__ float    gTpF[Kdim * Kdim]; // fp32 row-softmax of T (for bias kernel)
__device__ float    gLpi2[Kdim];       // log_softmax(pi) * log2(e)
__device__ float    gLs[Kdim];         // per-state log2 correction for bf16(T) bias
__device__ float    gPart[Bseq];

// ---------------------------------------------------------------------------
// helpers
// ---------------------------------------------------------------------------
__device__ __forceinline__ float ex2f(float x) {
    float r; asm("ex2.approx.ftz.f32 %0, %1;" : "=f"(r) : "f"(x)); return r;
}
__device__ __forceinline__ float lg2f(float x) {
    float r; asm("lg2.approx.ftz.f32 %0, %1;" : "=f"(r) : "f"(x)); return r;
}
__device__ __forceinline__ float warp_sum(float v) {
#pragma unroll
    for (int o = 16; o > 0; o >>= 1) v += __shfl_xor_sync(0xffffffffu, v, o);
    return v;
}
__device__ __forceinline__ void hfma2(unsigned& acc, unsigned a, unsigned b) {
    asm("fma.rn.bf16x2 %0, %1, %2, %0;" : "+r"(acc) : "r"(a), "r"(b));
}
__device__ __forceinline__ unsigned hadd2(unsigned a, unsigned b) {
    unsigned r; asm("add.rn.bf16x2 %0, %1, %2;" : "=r"(r) : "r"(a), "r"(b)); return r;
}
__device__ __forceinline__ float blo(unsigned u) { return __uint_as_float(u << 16); }
__device__ __forceinline__ float bhi(unsigned u) { return __uint_as_float(u & 0xffff0000u); }
__device__ __forceinline__ unsigned pack_bf16x2(float lo, float hi) {
    unsigned r; asm("cvt.rn.bf16x2.f32 %0, %1, %2;" : "=r"(r) : "f"(hi), "f"(lo)); return r;
}
__device__ __forceinline__ float bf16r(float x) { return blo(pack_bf16x2(x, 0.f)); }
__device__ __forceinline__ void cpasync16(void* dst, const void* src) {
    unsigned d = (unsigned)__cvta_generic_to_shared(dst);
    asm volatile("cp.async.ca.shared.global [%0], [%1], 16;" :: "r"(d), "l"(src));
}
template <int N> __device__ __forceinline__ void wait_group() {
    asm volatile("cp.async.wait_group %0;" :: "n"(N));
}
__device__ __forceinline__ void commit_group() {
    asm volatile("cp.async.commit_group;");
}

// issue one 32-step emission block (64 rows x 32 floats) into staging buffer
__device__ __forceinline__ void issue_stage(float* sbuf, const float* gbase, int l) {
#pragma unroll
    for (int i = 0; i < 16; i++) {
        int m   = (i << 5) + l;
        int row = m >> 3;
        int c4  = (m & 7) << 2;
        cpasync16(sbuf + row * STRIDE + c4, gbase + (size_t)row * Nn + c4);
    }
    commit_group();
}

// ---------------------------------------------------------------------------
// prep: softmax rows of T -> fp32 copy + bf16x2 pack; log_softmax(pi)
// ---------------------------------------------------------------------------
__global__ void __launch_bounds__(1024) prep_kernel(const float* __restrict__ pi,
                                                    const float* __restrict__ T) {
    __shared__ float sTp[Kdim * Kdim];
    int tid = threadIdx.x, w = tid >> 5, l = tid & 31;
#pragma unroll
    for (int r = w; r < Kdim; r += 32) {
        float a = T[r * Kdim + l], c = T[r * Kdim + l + 32];
        float m = fmaxf(a, c);
#pragma unroll
        for (int o = 16; o > 0; o >>= 1) m = fmaxf(m, __shfl_xor_sync(0xffffffffu, m, o));
        float ea = expf(a - m), ec = expf(c - m);
        float s = warp_sum(ea + ec);
        float inv = 1.0f / s;
        sTp[r * Kdim + l]      = ea * inv;
        sTp[r * Kdim + l + 32] = ec * inv;
    }
    __syncthreads();
    for (int idx = tid; idx < Kdim * Kdim; idx += 1024) gTpF[idx] = sTp[idx];
    for (int idx = tid; idx < Kdim * 32; idx += 1024) {
        int k = idx >> 5, j = idx & 31;
        gT2[idx] = pack_bf16x2(sTp[(2 * j) * Kdim + k], sTp[(2 * j + 1) * Kdim + k]);
    }
    if (w == 0) {  // log_softmax(pi)
        float pa = pi[l], pb = pi[l + 32];
        float m2 = fmaxf(pa, pb);
#pragma unroll
        for (int o = 16; o > 0; o >>= 1) m2 = fmaxf(m2, __shfl_xor_sync(0xffffffffu, m2, o));
        float sp = warp_sum(expf(pa - m2) + expf(pb - m2));
        float ls = logf(sp);
        gLpi2[l]      = (pa - m2 - ls) * L2E;
        gLpi2[l + 32] = (pb - m2 - ls) * L2E;
    }
}

// ---------------------------------------------------------------------------
// bias kernel (single warp): stationary distribution of Tp + per-column
// log2 correction for the coherent bf16(T) quantization bias
// ---------------------------------------------------------------------------
__global__ void bias_kernel() {
    int l = threadIdx.x;
    float wA = 1.0f / 64.0f, wB = 1.0f / 64.0f;
    for (int it = 0; it < 24; it++) {
        float nA = 0.f, nB = 0.f;
#pragma unroll
        for (int j = 0; j < 32; j++) {
            float wj0 = __shfl_sync(0xffffffffu, wA, j);
            float wj1 = __shfl_sync(0xffffffffu, wB, j);
            nA = fmaf(wj0, gTpF[(2 * j) * Kdim + 2 * l],     nA);
            nA = fmaf(wj1, gTpF[(2 * j + 1) * Kdim + 2 * l], nA);
            nB = fmaf(wj0, gTpF[(2 * j) * Kdim + 2 * l + 1],     nB);
            nB = fmaf(wj1, gTpF[(2 * j + 1) * Kdim + 2 * l + 1], nB);
        }
        float S = warp_sum(nA + nB);
        wA = nA / S; wB = nB / S;
    }
    float nA = 0.f, nB = 0.f, dA = 0.f, dB = 0.f;
#pragma unroll
    for (int j = 0; j < 32; j++) {
        float wj0 = __shfl_sync(0xffffffffu, wA, j);
        float wj1 = __shfl_sync(0xffffffffu, wB, j);
        float t00 = gTpF[(2 * j) * Kdim + 2 * l];
        float t10 = gTpF[(2 * j + 1) * Kdim + 2 * l];
        float t01 = gTpF[(2 * j) * Kdim + 2 * l + 1];
        float t11 = gTpF[(2 * j + 1) * Kdim + 2 * l + 1];
        nA += wj0 * t00 + wj1 * t10;
        nB += wj0 * t01 + wj1 * t11;
        dA += wj0 * bf16r(t00) + wj1 * bf16r(t10);
        dB += wj0 * bf16r(t01) + wj1 * bf16r(t11);
    }
    gLs[2 * l]     = log2f(nA / dA);
    gLs[2 * l + 1] = log2f(nB / dB);
}

// ---------------------------------------------------------------------------
// one forward step: smem ping-pong exchange, depth-8 bf16 accumulation
// (8 accumulators -> shallow chains -> small coherent rounding bias).
// lane l owns states (2l, 2l+1).
// ---------------------------------------------------------------------------
__device__ __forceinline__ void step(const unsigned* qR, unsigned* qW, int l,
                                     const unsigned* Ta, const unsigned* Tb,
                                     float eA, float eB, float gpA, float gpB,
                                     float& qA, float& qB) {
    __syncwarp();
    const uint4* qp = (const uint4*)qR;
    unsigned A0 = 0, A1 = 0, A2 = 0, A3 = 0;
    unsigned B0 = 0, B1 = 0, B2 = 0, B3 = 0;
#pragma unroll
    for (int i = 0; i < 8; i++) {
        uint4 w = qp[i];
        hfma2(A0, w.x, Ta[4 * i + 0]);  hfma2(B0, w.x, Tb[4 * i + 0]);
        hfma2(A1, w.y, Ta[4 * i + 1]);  hfma2(B1, w.y, Tb[4 * i + 1]);
        hfma2(A2, w.z, Ta[4 * i + 2]);  hfma2(B2, w.z, Tb[4 * i + 2]);
        hfma2(A3, w.w, Ta[4 * i + 3]);  hfma2(B3, w.w, Tb[4 * i + 3]);
    }
    unsigned a = hadd2(hadd2(A0, A1), hadd2(A2, A3));
    unsigned b = hadd2(hadd2(B0, B1), hadd2(B2, B3));
    float dA = blo(a) + bhi(a);          // fp32 final combine
    float dB = blo(b) + bhi(b);
    float fA = ex2f(fmaf(eA, L2E, gpA));
    float fB = ex2f(fmaf(eB, L2E, gpB));
    qA = fA * dA;
    qB = fB * dB;
    qW[l] = pack_bf16x2(qA, qB);
}

// ---------------------------------------------------------------------------
// forward scan: one single-warp CTA per sequence (1024 CTAs)
// ---------------------------------------------------------------------------
__global__ void __launch_bounds__(32) fwd_kernel(const float* __restrict__ lp) {
    __shared__ float st[2][Kdim * STRIDE];
    __shared__ __align__(16) unsigned q0[32], q1[32];
    const int l = threadIdx.x;
    const int b = blockIdx.x;
    const float* base = lp + (size_t)b * NSs;

    issue_stage(st[0], base, l);
    issue_stage(st[1], base + TBLK, l);

    unsigned Ta[32], Tb[32];
    {
        const uint4* pa = (const uint4*)(gT2 + (2 * l) * 32);
        const uint4* pb = (const uint4*)(gT2 + (2 * l + 1) * 32);
#pragma unroll
        for (int i = 0; i < 8; i++) { ((uint4*)Ta)[i] = pa[i]; ((uint4*)Tb)[i] = pb[i]; }
    }
    const float lpiA = gLpi2[2 * l], lpiB = gLpi2[2 * l + 1];
    const float lsA  = gLs[2 * l],   lsB  = gLs[2 * l + 1];

    wait_group<1>();
    __syncwarp();

    // t = 0: q = exp2(lp0*log2e + log2_pi); then t = 1..3 (live q ends in q1)
    float4 e4A = *(const float4*)(st[0] + (2 * l) * STRIDE);
    float4 e4B = *(const float4*)(st[0] + (2 * l + 1) * STRIDE);
    float qA = ex2f(fmaf(e4A.x, L2E, lpiA));
    float qB = ex2f(fmaf(e4B.x, L2E, lpiB));
    q0[l] = pack_bf16x2(qA, qB);
    step(q0, q1, l, Ta, Tb, e4A.y, e4B.y, lsA, lsB, qA, qB);
    step(q1, q0, l, Ta, Tb, e4A.z, e4B.z, lsA, lsB, qA, qB);
    step(q0, q1, l, Ta, Tb, e4A.w, e4B.w, lsA, lsB, qA, qB);

    double cacc = 0.0;
    float  gp   = 0.0f;   // pending -log2(scale) from the last block's renorm

#pragma unroll 1
    for (int t0 = 4; t0 < NSs; t0 += 4) {
        if ((t0 & (TBLK - 1)) == 0) {
            // block boundary: renorm every 32 steps, co-located with the
            // staging wait so the warp_sum+lg2 chain hides behind the stall
            float S = warp_sum(qA + qB);
            float g = lg2f(S);
            cacc += (double)g;
            gp = -g;
            wait_group<0>();
            __syncwarp();
            int k = t0 >> 5;
            if (t0 + TBLK < NSs)
                issue_stage(st[(k + 1) & 1], base + t0 + TBLK, l);
        }
        const float* sb = st[(t0 >> 5) & 1];
        const int tt = t0 & (TBLK - 1);
        float4 eA = *(const float4*)(sb + (2 * l) * STRIDE + tt);
        float4 eB = *(const float4*)(sb + (2 * l + 1) * STRIDE + tt);

        // groups always start with live q in q1 (4 swaps return it to q1)
        step(q1, q0, l, Ta, Tb, eA.x, eB.x, lsA + gp, lsB + gp, qA, qB);
        step(q0, q1, l, Ta, Tb, eA.y, eB.y, lsA, lsB, qA, qB);
        step(q1, q0, l, Ta, Tb, eA.z, eB.z, lsA, lsB, qA, qB);
        step(q0, q1, l, Ta, Tb, eA.w, eB.w, lsA, lsB, qA, qB);
        gp = 0.0f;
    }

    float S = warp_sum(qA + qB);
    if (l == 0) gPart[b] = LN2 * (float)(cacc + (double)lg2f(S));
}

// ---------------------------------------------------------------------------
// deterministic final reduction
// ---------------------------------------------------------------------------
__global__ void reduce_kernel(float* __restrict__ out) {
    __shared__ double s[256];
    int t = threadIdx.x;
    double v = 0.0;
    for (int i = t; i < Bseq; i += 256) v += (double)gPart[i];
    s[t] = v;
    __syncthreads();
    for (int o = 128; o > 0; o >>= 1) {
        if (t < o) s[t] += s[t + o];
        __syncthreads();
    }
    if (t == 0) out[0] = (float)s[0];
}

// ---------------------------------------------------------------------------
extern "C" void kernel_launch(void* const* d_in, const int* in_sizes, int n_in,
                              void* d_out, int out_size) {
    const float* lp = (const float*)d_in[0];  // log_pdf (K, N)
    const float* pi = (const float*)d_in[1];  // pi (K,)
    const float* T  = (const float*)d_in[2];  // T (K, K)
    (void)in_sizes; (void)n_in; (void)out_size;

    prep_kernel<<<1, 1024>>>(pi, T);
    bias_kernel<<<1, 32>>>();
    fwd_kernel<<<Bseq, 32>>>(lp);
    reduce_kernel<<<1, 256>>>((float*)d_out);
}